// round 12
// baseline (speedup 1.0000x reference)
#include <cuda_runtime.h>
#include <cstdint>

// Problem constants (fixed by reference _build_structures with seed 0)
#define GG       128
#define NPER     20
#define NNODES   (GG * NPER)          // 2560
#define P2       190
#define N2       (GG * P2)            // 24320
#define P3       1140
#define N3       (GG * P3)            // 145920
#define H        64
#define EMB_DIM  192
#define OUT_DIM  10
#define MAXDEG   64
#define L1_BLOCKS (NNODES / 64)       // 40

// -------- scratch (static device globals; no runtime allocation) --------
__device__ float d_hA[NNODES * H];
__device__ float d_hB[NNODES * H];
__device__ float d_hC[NNODES * H];      // post-relu h1 for levels 2/3
__device__ float d_msg1[NNODES * H];
__device__ float d_msg1b[NNODES * H];

__device__ float d_y2[N2 * H];
__device__ float d_msg2[N2 * H];
__device__ float d_h2[N2 * H];

__device__ float d_y3[N3 * H];
__device__ float d_msg3[N3 * H];
__device__ float d_h3[N3 * H];

__device__ float d_emb[GG * EMB_DIM];
__device__ float d_Wt[160 * 128];

__device__ int   d_cnt1[NNODES];
__device__ int   d_csr1[NNODES * MAXDEG];
__device__ int   d_cnt2[N2];
__device__ int   d_csr2[N2 * MAXDEG];
__device__ int   d_cnt3[N3];
__device__ int   d_csr3[N3 * MAXDEG];

// software grid barrier state (zero-initialized; count self-resets each use,
// gen grows monotonically across barriers and graph replays — deterministic)
__device__ unsigned d_barCount;
__device__ unsigned d_barGen;

// ============================================================
// helpers
// ============================================================
__device__ __forceinline__ uint32_t f2tf32(float f) {
    uint32_t u;
    asm("cvt.rna.tf32.f32 %0, %1;" : "=r"(u) : "f"(f));
    return u;
}
__device__ __forceinline__ uint32_t f2tf32_relu(float f) {
    return f2tf32(fmaxf(f, 0.f));
}
__device__ __forceinline__ void mma_tf32(float* c, const uint32_t* a, const uint32_t* b) {
    asm volatile(
        "mma.sync.aligned.m16n8k8.row.col.f32.tf32.tf32.f32 "
        "{%0,%1,%2,%3}, {%4,%5,%6,%7}, {%8,%9}, {%0,%1,%2,%3};"
        : "+f"(c[0]), "+f"(c[1]), "+f"(c[2]), "+f"(c[3])
        : "r"(a[0]), "r"(a[1]), "r"(a[2]), "r"(a[3]), "r"(b[0]), "r"(b[1]));
}
__device__ __forceinline__ void red4(float* p, float4 v) {
    asm volatile("red.global.add.v4.f32 [%0], {%1,%2,%3,%4};"
                 :: "l"(p), "f"(v.x), "f"(v.y), "f"(v.z), "f"(v.w) : "memory");
}

__device__ __forceinline__ void grid_barrier() {
    __syncthreads();
    __threadfence();
    if (threadIdx.x == 0) {
        unsigned g = atomicAdd(&d_barGen, 0u);
        if (atomicAdd(&d_barCount, 1u) == L1_BLOCKS - 1) {
            atomicExch(&d_barCount, 0u);
            __threadfence();
            atomicAdd(&d_barGen, 1u);
        } else {
            while (atomicAdd(&d_barGen, 0u) == g) { }
        }
    }
    __syncthreads();
    __threadfence();
}

// ============================================================
// CSR-by-dst build
// ============================================================
__global__ void csr_fill(const int* __restrict__ key, const int* __restrict__ val,
                         int E, int* __restrict__ cnt, int* __restrict__ csr) {
    int e = blockIdx.x * blockDim.x + threadIdx.x;
    if (e >= E) return;
    int d = key[e];
    int slot = atomicAdd(&cnt[d], 1);
    csr[(size_t)d * MAXDEG + slot] = val[e];
}

// ============================================================
// gather_add: OUT[r] = Y1[r] + sum_{s in in(r)} MSG[s]  (16 thr/row)
// ============================================================
__global__ void gather_add(const float4* __restrict__ Y1,
                           const float4* __restrict__ MSG,
                           const int* __restrict__ cnt, const int* __restrict__ csr,
                           int N, float4* __restrict__ OUT) {
    long long idx = (long long)blockIdx.x * blockDim.x + threadIdx.x;
    int row = (int)(idx >> 4);
    if (row >= N) return;
    int c = (int)(idx & 15);
    float4 acc = Y1[(size_t)row * 16 + c];
    int deg = cnt[row];
    const int* lst = csr + (size_t)row * MAXDEG;
    for (int e = 0; e < deg; e++) {
        float4 v = MSG[(size_t)lst[e] * 16 + c];
        acc.x += v.x; acc.y += v.y; acc.z += v.z; acc.w += v.w;
    }
    OUT[(size_t)row * 16 + c] = acc;
}

// ============================================================
// gather_emb: per-graph sum of relu(Y1[r] + sum_in MSG) red-added into emb
// ============================================================
__global__ void gather_emb(const float4* __restrict__ Y1,
                           const float4* __restrict__ MSG,
                           const int* __restrict__ cnt, const int* __restrict__ csr,
                           int N, int rpg, float* __restrict__ emb, int colOff) {
    long long idx = (long long)blockIdx.x * blockDim.x + threadIdx.x;
    int row = (int)(idx >> 4);
    if (row >= N) return;
    int c = (int)(idx & 15);
    float4 acc = Y1[(size_t)row * 16 + c];
    int deg = cnt[row];
    const int* lst = csr + (size_t)row * MAXDEG;
    for (int e = 0; e < deg; e++) {
        float4 v = MSG[(size_t)lst[e] * 16 + c];
        acc.x += v.x; acc.y += v.y; acc.z += v.z; acc.w += v.w;
    }
    acc.x = fmaxf(acc.x, 0.f); acc.y = fmaxf(acc.y, 0.f);
    acc.z = fmaxf(acc.z, 0.f); acc.w = fmaxf(acc.w, 0.f);
    int g = row / rpg;
    red4(emb + (size_t)g * EMB_DIM + colOff + c * 4, acc);
}

// ============================================================
// tf32 mma.sync dual GEMM, split-K phased staging (R8/R10-verified).
// MODE 0: contiguous rows (KP == K), optional relu.
// MODE 2: [h[ia], h[ib]] + iso scalar; K=128, KP=64.
// MODE 3: [h[ia], h[ib], h[ic]] + iso one-hot; K=192, KP=96.
// ============================================================
template <int K, int KP, int MODE>
__global__ void __launch_bounds__(256)
gemm_mma(const float* __restrict__ X,
         const int* __restrict__ ia, const int* __restrict__ ib,
         const int* __restrict__ ic,
         const float* __restrict__ iso,
         const float* __restrict__ Wa, const float* __restrict__ Wb, int wK,
         float* __restrict__ Y1, float* __restrict__ MSG, int reluIn) {
    extern __shared__ float sm[];
    constexpr int SA  = KP + 4;
    constexpr int NPH = K / KP;
    float* As   = sm;                    // [128][SA]
    float* Bs   = sm + 128 * SA;         // [KP][136]
    float* isoT = Bs + KP * 136;         // MODE3: [128][4] ; MODE2: [128]

    const int t = threadIdx.x;
    const int rowBase = blockIdx.x * 128;

    const int lane = t & 31;
    const int wid = t >> 5;
    const int wm = (wid & 3) * 32;
    const int wn = (wid >> 2) * 64;
    const int ar = lane >> 2, ak = lane & 3;
    const int bc = lane >> 2, bk = lane & 3;

    float acc[2][8][4];
#pragma unroll
    for (int mt = 0; mt < 2; mt++)
#pragma unroll
        for (int nt = 0; nt < 8; nt++) {
            acc[mt][nt][0] = 0.f; acc[mt][nt][1] = 0.f;
            acc[mt][nt][2] = 0.f; acc[mt][nt][3] = 0.f;
        }

#pragma unroll
    for (int ph = 0; ph < NPH; ph++) {
        // ---- stage B phase (tf32). float4 only when wK % 4 == 0. ----
        {
            constexpr int K4 = KP / 4;
            const bool vec4 = ((wK & 3) == 0);
            for (int i = t; i < 128 * K4; i += 256) {
                int j = i / K4;
                int k = (i - j * K4) * 4;
                int gk = ph * KP + k;
                const float* src = (j < 64) ? (Wa + (size_t)j * wK)
                                            : (Wb + (size_t)(j - 64) * wK);
                float4 v;
                if (vec4) {
                    v = *(const float4*)(src + gk);
                } else {
                    v.x = src[gk]; v.y = src[gk + 1]; v.z = src[gk + 2]; v.w = src[gk + 3];
                }
                Bs[(k + 0) * 136 + j] = __uint_as_float(f2tf32(v.x));
                Bs[(k + 1) * 136 + j] = __uint_as_float(f2tf32(v.y));
                Bs[(k + 2) * 136 + j] = __uint_as_float(f2tf32(v.z));
                Bs[(k + 3) * 136 + j] = __uint_as_float(f2tf32(v.w));
            }
            if (ph == 0) {
                if (MODE == 3) {
                    for (int i = t; i < 512; i += 256) {
                        int j = i >> 2, e = i & 3;
                        const float* src = (j < 64) ? (Wa + (size_t)j * wK)
                                                    : (Wb + (size_t)(j - 64) * wK);
                        isoT[j * 4 + e] = src[K + e];
                    }
                } else if (MODE == 2) {
                    if (t < 128) {
                        const float* src = (t < 64) ? (Wa + (size_t)t * wK)
                                                    : (Wb + (size_t)(t - 64) * wK);
                        isoT[t] = src[K];
                    }
                }
            }
        }

        // ---- stage A phase (relu + tf32) ----
        if (MODE == 0) {
            constexpr int K4 = KP / 4;
            for (int i = t; i < 128 * K4; i += 256) {
                int row = i / K4;
                int k = (i - row * K4) * 4;
                float4 v = *(const float4*)(X + (size_t)(rowBase + row) * K + ph * KP + k);
                uint4 u;
                if (reluIn) {
                    u.x = f2tf32_relu(v.x); u.y = f2tf32_relu(v.y);
                    u.z = f2tf32_relu(v.z); u.w = f2tf32_relu(v.w);
                } else {
                    u.x = f2tf32(v.x); u.y = f2tf32(v.y);
                    u.z = f2tf32(v.z); u.w = f2tf32(v.w);
                }
                *(uint4*)(As + row * SA + k) = u;
            }
        } else if (MODE == 2) {
            const int r = t >> 1, half = t & 1;
            const int* idxp = (ph == 0) ? ia : ib;
            int srcRow = idxp[rowBase + r];
            const float4* src = (const float4*)(X + (size_t)srcRow * 64) + half * 8;
#pragma unroll
            for (int i = 0; i < 8; i++) {
                float4 v = src[i];
                uint4 u;
                u.x = f2tf32_relu(v.x); u.y = f2tf32_relu(v.y);
                u.z = f2tf32_relu(v.z); u.w = f2tf32_relu(v.w);
                *(uint4*)(As + r * SA + half * 32 + i * 4) = u;
            }
        } else {  // MODE 3, KP = 96
            const int r = t >> 1, half = t & 1;
#pragma unroll
            for (int c = 0; c < 12; c++) {
                int lk = half * 48 + c * 4;
                int gk = ph * KP + lk;
                int seg = gk >> 6;
                const int* idxp = (seg == 0) ? ia : (seg == 1) ? ib : ic;
                int srcRow = idxp[rowBase + r];
                float4 v = *(const float4*)(X + (size_t)srcRow * 64 + (gk & 63));
                uint4 u;
                u.x = f2tf32_relu(v.x); u.y = f2tf32_relu(v.y);
                u.z = f2tf32_relu(v.z); u.w = f2tf32_relu(v.w);
                *(uint4*)(As + r * SA + lk) = u;
            }
        }
        __syncthreads();

        // ---- compute over this phase ----
#pragma unroll 2
        for (int k0 = 0; k0 < KP; k0 += 8) {
            uint32_t af[2][4];
#pragma unroll
            for (int mt = 0; mt < 2; mt++) {
                const float* p = As + (wm + mt * 16 + ar) * SA + k0 + ak;
                af[mt][0] = __float_as_uint(p[0]);
                af[mt][1] = __float_as_uint(p[8 * SA]);
                af[mt][2] = __float_as_uint(p[4]);
                af[mt][3] = __float_as_uint(p[8 * SA + 4]);
            }
            uint32_t bf[8][2];
#pragma unroll
            for (int nt = 0; nt < 8; nt++) {
                const float* p = Bs + (k0 + bk) * 136 + wn + nt * 8 + bc;
                bf[nt][0] = __float_as_uint(p[0]);
                bf[nt][1] = __float_as_uint(p[4 * 136]);
            }
#pragma unroll
            for (int mt = 0; mt < 2; mt++)
#pragma unroll
                for (int nt = 0; nt < 8; nt++)
                    mma_tf32(acc[mt][nt], af[mt], bf[nt]);
        }
        if (ph + 1 < NPH) __syncthreads();
    }

    // ---- epilogue ----
    float* dstBase = (wid >> 2) ? MSG : Y1;
#pragma unroll
    for (int mt = 0; mt < 2; mt++) {
        int r0 = rowBase + wm + mt * 16 + (lane >> 2);
        int r1 = r0 + 8;
        int e0 = 0, e1 = 0;
        float s0 = 0.f, s1 = 0.f;
        if (MODE == 3) {
            float4 v0 = ((const float4*)iso)[r0];
            float4 v1 = ((const float4*)iso)[r1];
            e0 = (int)(v0.y + 2.f * v0.z + 3.f * v0.w + 0.5f);
            e1 = (int)(v1.y + 2.f * v1.z + 3.f * v1.w + 0.5f);
        } else if (MODE == 2) {
            s0 = iso[r0];
            s1 = iso[r1];
        }
        float* d0 = dstBase + (size_t)r0 * 64;
        float* d1 = dstBase + (size_t)r1 * 64;
#pragma unroll
        for (int nt = 0; nt < 8; nt++) {
            int gc = wn + nt * 8 + 2 * (lane & 3);
            int oc = gc & 63;
            float v0 = acc[mt][nt][0], v1 = acc[mt][nt][1];
            float v2 = acc[mt][nt][2], v3 = acc[mt][nt][3];
            if (MODE == 3) {
                v0 += isoT[gc * 4 + e0];       v1 += isoT[(gc + 1) * 4 + e0];
                v2 += isoT[gc * 4 + e1];       v3 += isoT[(gc + 1) * 4 + e1];
            } else if (MODE == 2) {
                v0 += s0 * isoT[gc];           v1 += s0 * isoT[gc + 1];
                v2 += s1 * isoT[gc];           v3 += s1 * isoT[gc + 1];
            }
            *(float2*)(d0 + oc) = make_float2(v0, v1);
            *(float2*)(d1 + oc) = make_float2(v2, v3);
        }
    }
}

// ============================================================
// weight prep (level-1 FFMA layers)
// ============================================================
struct WPrepAll {
    const float* w1[3];
    const float* w2[3];
    int K[3];
    int off[3];
};

__global__ void prep_weights(WPrepAll P, float* __restrict__ Wt) {
    int l = blockIdx.x;
    const float* __restrict__ w1 = P.w1[l];
    const float* __restrict__ w2 = P.w2[l];
    int K = P.K[l];
    float* out = Wt + (size_t)P.off[l] * 128;
    for (int i = threadIdx.x; i < K * 128; i += blockDim.x) {
        int k = i >> 7, j = i & 127;
        out[i] = (j < 64) ? w1[j * K + k] : w2[(j - 64) * K + k];
    }
}

// ============================================================
// level-1 persistent kernel: 3 FFMA dual-GEMM layers + CSR gathers +
// final h/emb reduction, one launch, software grid barriers.
// 40 CTAs x 256 threads, each CTA owns rows [blockIdx*64, +64).
// ============================================================
__device__ __forceinline__ void l1_compute_dual(
    const float* __restrict__ Xs, float* __restrict__ Wsh,
    const float* __restrict__ Wt, int K,
    float* __restrict__ Y1, float* __restrict__ MSG, int rowBase, int t) {
    const int cg = t & 31;
    const int rg = t >> 5;
    float acc[8][4];
#pragma unroll
    for (int r = 0; r < 8; r++) {
        acc[r][0] = acc[r][1] = acc[r][2] = acc[r][3] = 0.f;
    }
    const float* Xw = Xs + rg * 8 * K;

    for (int k0 = 0; k0 < K; k0 += 32) {
        __syncthreads();
        {
            const float4* s4 = (const float4*)(Wt + (size_t)k0 * 128);
            float4* d4 = (float4*)Wsh;
#pragma unroll
            for (int i = 0; i < 4; i++) d4[t + i * 256] = s4[t + i * 256];
        }
        __syncthreads();
#pragma unroll 8
        for (int kk = 0; kk < 32; kk++) {
            float4 wv = *(const float4*)(Wsh + kk * 128 + cg * 4);
#pragma unroll
            for (int r = 0; r < 8; r++) {
                float xv = Xw[r * K + k0 + kk];
                acc[r][0] += xv * wv.x;
                acc[r][1] += xv * wv.y;
                acc[r][2] += xv * wv.z;
                acc[r][3] += xv * wv.w;
            }
        }
    }

    float* outp = (cg < 16)
        ? (Y1  + (size_t)(rowBase + rg * 8) * 64 + cg * 4)
        : (MSG + (size_t)(rowBase + rg * 8) * 64 + (cg - 16) * 4);
#pragma unroll
    for (int r = 0; r < 8; r++) {
        float4 v;
        v.x = acc[r][0]; v.y = acc[r][1]; v.z = acc[r][2]; v.w = acc[r][3];
        *(float4*)(outp + (size_t)r * 64) = v;
    }
}

__device__ __forceinline__ void l1_gather_stage(
    float* __restrict__ Xs,
    const float4* __restrict__ Y, const float4* __restrict__ M,
    const int* __restrict__ cnt, const int* __restrict__ csr,
    int rowBase, int t) {
    const int r = t >> 2, q = t & 3;
    int row = rowBase + r;
    int deg = cnt[row];
    const int* lst = csr + (size_t)row * MAXDEG;
#pragma unroll
    for (int i = 0; i < 4; i++) {
        int c4 = i * 4 + q;
        float4 a4 = Y[(size_t)row * 16 + c4];
        for (int e = 0; e < deg; e++) {
            float4 v = M[(size_t)lst[e] * 16 + c4];
            a4.x += v.x; a4.y += v.y; a4.z += v.z; a4.w += v.w;
        }
        a4.x = fmaxf(a4.x, 0.f); a4.y = fmaxf(a4.y, 0.f);
        a4.z = fmaxf(a4.z, 0.f); a4.w = fmaxf(a4.w, 0.f);
        *(float4*)(Xs + r * 64 + c4 * 4) = a4;
    }
}

__global__ void __launch_bounds__(256)
level1_persist(const float* __restrict__ x,
               const int* __restrict__ cnt1, const int* __restrict__ csr1,
               const float* __restrict__ Wt,
               float* __restrict__ hA, float* __restrict__ msg1,
               float* __restrict__ hB, float* __restrict__ msg1b,
               float* __restrict__ hC, float* __restrict__ emb) {
    __shared__ float Xs[64 * 64];
    __shared__ float Wsh[32 * 128];
    const int t = threadIdx.x;
    const int rowBase = blockIdx.x * 64;

    // ---- layer 0: stage x (K=32, no relu) ----
    {
        const float4* src = (const float4*)(x + (size_t)rowBase * 32);
        for (int i = t; i < 64 * 8; i += 256) ((float4*)Xs)[i] = src[i];
    }
    l1_compute_dual(Xs, Wsh, Wt + 0 * 128, 32, hA, msg1, rowBase, t);
    grid_barrier();

    // ---- layer 1: gather-stage from (hA, msg1) ----
    l1_gather_stage(Xs, (const float4*)hA, (const float4*)msg1, cnt1, csr1, rowBase, t);
    l1_compute_dual(Xs, Wsh, Wt + 32 * 128, 64, hB, msg1b, rowBase, t);
    grid_barrier();

    // ---- layer 2: gather-stage from (hB, msg1b) ----
    l1_gather_stage(Xs, (const float4*)hB, (const float4*)msg1b, cnt1, csr1, rowBase, t);
    l1_compute_dual(Xs, Wsh, Wt + 96 * 128, 64, hA, msg1, rowBase, t);
    grid_barrier();

    // ---- tail: h = relu(hA + gather(msg1)) -> hC, emb cols 0..63 ----
    {
        const int r = t >> 2, q = t & 3;
        int row = rowBase + r;
        int deg = cnt1[row];
        const int* lst = csr1 + (size_t)row * MAXDEG;
        int g = row / NPER;
#pragma unroll
        for (int i = 0; i < 4; i++) {
            int c4 = i * 4 + q;
            float4 a4 = ((const float4*)hA)[(size_t)row * 16 + c4];
            for (int e = 0; e < deg; e++) {
                float4 v = ((const float4*)msg1)[(size_t)lst[e] * 16 + c4];
                a4.x += v.x; a4.y += v.y; a4.z += v.z; a4.w += v.w;
            }
            a4.x = fmaxf(a4.x, 0.f); a4.y = fmaxf(a4.y, 0.f);
            a4.z = fmaxf(a4.z, 0.f); a4.w = fmaxf(a4.w, 0.f);
            ((float4*)hC)[(size_t)row * 16 + c4] = a4;
            red4(emb + (size_t)g * EMB_DIM + c4 * 4, a4);
        }
    }
}

// ---------------- classifier head ----------------
__global__ void head(const float* __restrict__ emb,
                     const float* __restrict__ cW1, const float* __restrict__ cb1,
                     const float* __restrict__ cW2, const float* __restrict__ cb2,
                     float* __restrict__ out) {
    __shared__ float e[EMB_DIM];
    __shared__ float hid[H];
    int g = blockIdx.x;
    int t = threadIdx.x;
    for (int k = t; k < EMB_DIM; k += H) e[k] = emb[g * EMB_DIM + k];
    __syncthreads();
    float a = cb1[t];
    const float* w = cW1 + t * EMB_DIM;
#pragma unroll 4
    for (int k = 0; k < EMB_DIM; k++) a += e[k] * w[k];
    hid[t] = fmaxf(a, 0.f);
    __syncthreads();
    if (t < OUT_DIM) {
        float a2 = cb2[t];
        const float* w2 = cW2 + t * H;
#pragma unroll 8
        for (int k = 0; k < H; k++) a2 += hid[k] * w2[k];
        out[g * OUT_DIM + t] = a2;
    }
}

// ---------------- launch ----------------
extern "C" void kernel_launch(void* const* d_in, const int* in_sizes, int n_in,
                              void* d_out, int out_size) {
    const float* x           = (const float*)d_in[0];
    const int*   edge_index  = (const int*)d_in[1];
    const int*   gu2         = (const int*)d_in[3];
    const int*   gv2         = (const int*)d_in[4];
    const float* iso2        = (const float*)d_in[5];
    const int*   two_edges   = (const int*)d_in[6];
    const int*   ga3         = (const int*)d_in[8];
    const int*   gb3         = (const int*)d_in[9];
    const int*   gc3         = (const int*)d_in[10];
    const float* iso3        = (const float*)d_in[11];
    const int*   three_edges = (const int*)d_in[12];
    const float* g1W1_0 = (const float*)d_in[14];
    const float* g1W2_0 = (const float*)d_in[15];
    const float* g1W1_1 = (const float*)d_in[16];
    const float* g1W2_1 = (const float*)d_in[17];
    const float* g1W1_2 = (const float*)d_in[18];
    const float* g1W2_2 = (const float*)d_in[19];
    const float* g2W1_0 = (const float*)d_in[20];
    const float* g2W2_0 = (const float*)d_in[21];
    const float* g2W1_1 = (const float*)d_in[22];
    const float* g2W2_1 = (const float*)d_in[23];
    const float* g3W1_0 = (const float*)d_in[24];
    const float* g3W2_0 = (const float*)d_in[25];
    const float* g3W1_1 = (const float*)d_in[26];
    const float* g3W2_1 = (const float*)d_in[27];
    const float* cW1    = (const float*)d_in[28];
    const float* cb1    = (const float*)d_in[29];
    const float* cW2    = (const float*)d_in[30];
    const float* cb2    = (const float*)d_in[31];
    float* out = (float*)d_out;

    const int E1 = in_sizes[1] / 2;
    const int E2 = in_sizes[6] / 2;
    const int E3 = in_sizes[12] / 2;

    float *hA, *hB, *hC, *msg1, *msg1b, *y2, *msg2, *h2, *y3, *msg3, *h3, *emb, *Wt;
    int *cnt1, *csr1, *cnt2, *csr2, *cnt3, *csr3;
    cudaGetSymbolAddress((void**)&hA,    d_hA);
    cudaGetSymbolAddress((void**)&hB,    d_hB);
    cudaGetSymbolAddress((void**)&hC,    d_hC);
    cudaGetSymbolAddress((void**)&msg1,  d_msg1);
    cudaGetSymbolAddress((void**)&msg1b, d_msg1b);
    cudaGetSymbolAddress((void**)&y2,    d_y2);
    cudaGetSymbolAddress((void**)&msg2,  d_msg2);
    cudaGetSymbolAddress((void**)&h2,    d_h2);
    cudaGetSymbolAddress((void**)&y3,    d_y3);
    cudaGetSymbolAddress((void**)&msg3,  d_msg3);
    cudaGetSymbolAddress((void**)&h3,    d_h3);
    cudaGetSymbolAddress((void**)&emb,   d_emb);
    cudaGetSymbolAddress((void**)&Wt,    d_Wt);
    cudaGetSymbolAddress((void**)&cnt1,  d_cnt1);
    cudaGetSymbolAddress((void**)&csr1,  d_csr1);
    cudaGetSymbolAddress((void**)&cnt2,  d_cnt2);
    cudaGetSymbolAddress((void**)&csr2,  d_csr2);
    cudaGetSymbolAddress((void**)&cnt3,  d_cnt3);
    cudaGetSymbolAddress((void**)&csr3,  d_csr3);

    // dynamic smem opt-in
    const int SM_K192 = (128 * 100 + 96 * 136 + 512) * 4;   // 105472 -> 2 CTAs/SM
    const int SM_K128 = (128 * 68  + 64 * 136 + 128) * 4;   // 70144
    const int SM_K64  = (128 * 68  + 64 * 136) * 4;         // 69632
    cudaFuncSetAttribute((const void*)gemm_mma<192, 96, 3>,
                         cudaFuncAttributeMaxDynamicSharedMemorySize, SM_K192);
    cudaFuncSetAttribute((const void*)gemm_mma<128, 64, 2>,
                         cudaFuncAttributeMaxDynamicSharedMemorySize, SM_K128);
    cudaFuncSetAttribute((const void*)gemm_mma<64, 64, 0>,
                         cudaFuncAttributeMaxDynamicSharedMemorySize, SM_K64);

    // ---- prep: emb zero, cnt zeros, weight transpose, CSR builds ----
    cudaMemsetAsync(emb, 0, GG * EMB_DIM * sizeof(float));
    cudaMemsetAsync(cnt1, 0, NNODES * sizeof(int));
    cudaMemsetAsync(cnt2, 0, N2 * sizeof(int));
    cudaMemsetAsync(cnt3, 0, N3 * sizeof(int));

    WPrepAll P;
    P.w1[0] = g1W1_0; P.w2[0] = g1W2_0; P.K[0] = 32; P.off[0] = 0;
    P.w1[1] = g1W1_1; P.w2[1] = g1W2_1; P.K[1] = 64; P.off[1] = 32;
    P.w1[2] = g1W1_2; P.w2[2] = g1W2_2; P.K[2] = 64; P.off[2] = 96;
    prep_weights<<<3, 256>>>(P, Wt);

    csr_fill<<<(E1 + 255) / 256, 256>>>(edge_index + E1, edge_index, E1, cnt1, csr1);
    csr_fill<<<(E2 + 255) / 256, 256>>>(two_edges + E2, two_edges, E2, cnt2, csr2);
    csr_fill<<<(E3 + 255) / 256, 256>>>(three_edges + E3, three_edges, E3, cnt3, csr3);

    auto ga_grid = [](int N) { return (int)(((long long)N * 16 + 255) / 256); };

    // ---- level 1: one persistent kernel (3 layers + hC + emb cols 0..63) ----
    level1_persist<<<L1_BLOCKS, 256>>>(x, cnt1, csr1, Wt,
                                       hA, msg1, hB, msg1b, hC, emb);

    // ---- level 2 (2 layers, tf32 mma + gathers) ----
    gemm_mma<128, 64, 2><<<N2 / 128, 256, SM_K128>>>(hC, gu2, gv2, nullptr, iso2,
                                                     g2W1_0, g2W2_0, 129,
                                                     y2, msg2, 1);
    gather_add<<<ga_grid(N2), 256>>>((const float4*)y2, (const float4*)msg2,
                                     cnt2, csr2, N2, (float4*)h2);

    gemm_mma<64, 64, 0><<<N2 / 128, 256, SM_K64>>>(h2, nullptr, nullptr, nullptr, nullptr,
                                                   g2W1_1, g2W2_1, 64,
                                                   y2, msg2, 1);
    gather_emb<<<ga_grid(N2), 256>>>((const float4*)y2, (const float4*)msg2,
                                     cnt2, csr2, N2, P2, emb, H);

    // ---- level 3 (2 layers, tf32 mma + gathers) ----
    gemm_mma<192, 96, 3><<<N3 / 128, 256, SM_K192>>>(hC, ga3, gb3, gc3, iso3,
                                                     g3W1_0, g3W2_0, 196,
                                                     y3, msg3, 1);
    gather_add<<<ga_grid(N3), 256>>>((const float4*)y3, (const float4*)msg3,
                                     cnt3, csr3, N3, (float4*)h3);

    gemm_mma<64, 64, 0><<<N3 / 128, 256, SM_K64>>>(h3, nullptr, nullptr, nullptr, nullptr,
                                                   g3W1_1, g3W2_1, 64,
                                                   y3, msg3, 1);
    gather_emb<<<ga_grid(N3), 256>>>((const float4*)y3, (const float4*)msg3,
                                     cnt3, csr3, N3, P3, emb, 2 * H);

    // ---- head ----
    head<<<GG, H>>>(emb, cW1, cb1, cW2, cb2, out);
}

// round 13
// speedup vs baseline: 1.0394x; 1.0394x over previous
#include <cuda_runtime.h>
#include <cstdint>

// Problem constants (fixed by reference _build_structures with seed 0)
#define GG       128
#define NPER     20
#define NNODES   (GG * NPER)          // 2560
#define P2       190
#define N2       (GG * P2)            // 24320
#define P3       1140
#define N3       (GG * P3)            // 145920
#define H        64
#define EMB_DIM  192
#define OUT_DIM  10
#define MAXDEG   64                   // in-degree bound: <= 3*(NPER-3) = 51

// -------- scratch (static device globals; no runtime allocation) --------
__device__ float d_hA[NNODES * H];
__device__ float d_hB[NNODES * H];
__device__ float d_msg1[NNODES * H];

__device__ float d_y2[N2 * H];
__device__ float d_msg2[N2 * H];
__device__ float d_h2[N2 * H];

__device__ float d_y3[N3 * H];
__device__ float d_msg3[N3 * H];
__device__ float d_h3[N3 * H];

__device__ float d_emb[GG * EMB_DIM];
__device__ float d_Wt[160 * 128];

__device__ int   d_cnt2[N2];
__device__ int   d_csr2[N2 * MAXDEG];
__device__ int   d_cnt3[N3];
__device__ int   d_csr3[N3 * MAXDEG];

// ============================================================
// helpers
// ============================================================
__device__ __forceinline__ uint32_t f2tf32(float f) {
    uint32_t u;
    asm("cvt.rna.tf32.f32 %0, %1;" : "=r"(u) : "f"(f));
    return u;
}
__device__ __forceinline__ uint32_t f2tf32_relu(float f) {
    return f2tf32(fmaxf(f, 0.f));
}
__device__ __forceinline__ void mma_tf32(float* c, const uint32_t* a, const uint32_t* b) {
    asm volatile(
        "mma.sync.aligned.m16n8k8.row.col.f32.tf32.tf32.f32 "
        "{%0,%1,%2,%3}, {%4,%5,%6,%7}, {%8,%9}, {%0,%1,%2,%3};"
        : "+f"(c[0]), "+f"(c[1]), "+f"(c[2]), "+f"(c[3])
        : "r"(a[0]), "r"(a[1]), "r"(a[2]), "r"(a[3]), "r"(b[0]), "r"(b[1]));
}
__device__ __forceinline__ void red4(float* p, float4 v) {
    asm volatile("red.global.add.v4.f32 [%0], {%1,%2,%3,%4};"
                 :: "l"(p), "f"(v.x), "f"(v.y), "f"(v.z), "f"(v.w) : "memory");
}

// ============================================================
// prep_all: one launch zeroing cnt2/cnt3/emb AND transposing the 3
// level-1 weight pairs into Wt.
// block roles: [0, ZB2) zero cnt2; [ZB2, ZB3) zero cnt3; ZB3 zero emb;
//              ZB3+1 .. ZB3+3 weight transpose (l = 0..2).
// ============================================================
#define ZB2 12                         // 12*8192 > N2
#define ZB3 (ZB2 + 72)                 // 72*2048 ints... use strided loops anyway
struct WPrepAll {
    const float* w1[3];
    const float* w2[3];
    int K[3];
    int off[3];
};

__global__ void prep_all(WPrepAll P, float* __restrict__ Wt,
                         int* __restrict__ cnt2, int* __restrict__ cnt3,
                         float* __restrict__ emb) {
    int b = blockIdx.x;
    int t = threadIdx.x;
    if (b < ZB2) {
        for (int i = b * 256 + t; i < N2; i += ZB2 * 256) cnt2[i] = 0;
    } else if (b < ZB3) {
        int bb = b - ZB2;
        for (int i = bb * 256 + t; i < N3; i += (ZB3 - ZB2) * 256) cnt3[i] = 0;
    } else if (b == ZB3) {
        for (int i = t; i < GG * EMB_DIM; i += 256) emb[i] = 0.f;
    } else {
        int l = b - ZB3 - 1;   // 0..2
        const float* __restrict__ w1 = P.w1[l];
        const float* __restrict__ w2 = P.w2[l];
        int K = P.K[l];
        float* out = Wt + (size_t)P.off[l] * 128;
        for (int i = t; i < K * 128; i += 256) {
            int k = i >> 7, j = i & 127;
            out[i] = (j < 64) ? w1[j * K + k] : w2[(j - 64) * K + k];
        }
    }
}

// ============================================================
// merged CSR-by-dst build for levels 2 and 3; 4 edges per thread (MLP)
// ============================================================
__global__ void csr_fill2(const int* __restrict__ key2, const int* __restrict__ val2,
                          int E2v, int* __restrict__ cnt2v, int* __restrict__ csr2v,
                          const int* __restrict__ key3, const int* __restrict__ val3,
                          int E3v, int* __restrict__ cnt3v, int* __restrict__ csr3v,
                          int blocks2) {
    const int b = blockIdx.x;
    const int* __restrict__ key;
    const int* __restrict__ val;
    int* __restrict__ cnt;
    int* __restrict__ csr;
    int E, base;
    if (b < blocks2) {
        key = key2; val = val2; cnt = cnt2v; csr = csr2v; E = E2v;
        base = (b * 256 + threadIdx.x) * 4;
    } else {
        key = key3; val = val3; cnt = cnt3v; csr = csr3v; E = E3v;
        base = ((b - blocks2) * 256 + threadIdx.x) * 4;
    }
    if (base >= E) return;
    int n = min(4, E - base);
    int ks[4], vs[4];
#pragma unroll
    for (int i = 0; i < 4; i++) {
        if (i < n) { ks[i] = key[base + i]; vs[i] = val[base + i]; }
    }
#pragma unroll
    for (int i = 0; i < 4; i++) {
        if (i < n) {
            int slot = atomicAdd(&cnt[ks[i]], 1);
            csr[(size_t)ks[i] * MAXDEG + slot] = vs[i];
        }
    }
}

// ============================================================
// gather_add: OUT[r] = Y1[r] + sum_{s in in(r)} MSG[s]  (16 thr/row, 2x unroll)
// ============================================================
__global__ void gather_add(const float4* __restrict__ Y1,
                           const float4* __restrict__ MSG,
                           const int* __restrict__ cnt, const int* __restrict__ csr,
                           int N, float4* __restrict__ OUT) {
    long long idx = (long long)blockIdx.x * blockDim.x + threadIdx.x;
    int row = (int)(idx >> 4);
    if (row >= N) return;
    int c = (int)(idx & 15);
    float4 acc = Y1[(size_t)row * 16 + c];
    float4 acc2 = make_float4(0.f, 0.f, 0.f, 0.f);
    int deg = cnt[row];
    const int* lst = csr + (size_t)row * MAXDEG;
    int e = 0;
    for (; e + 2 <= deg; e += 2) {
        float4 v0 = MSG[(size_t)lst[e] * 16 + c];
        float4 v1 = MSG[(size_t)lst[e + 1] * 16 + c];
        acc.x += v0.x; acc.y += v0.y; acc.z += v0.z; acc.w += v0.w;
        acc2.x += v1.x; acc2.y += v1.y; acc2.z += v1.z; acc2.w += v1.w;
    }
    if (e < deg) {
        float4 v = MSG[(size_t)lst[e] * 16 + c];
        acc.x += v.x; acc.y += v.y; acc.z += v.z; acc.w += v.w;
    }
    acc.x += acc2.x; acc.y += acc2.y; acc.z += acc2.z; acc.w += acc2.w;
    OUT[(size_t)row * 16 + c] = acc;
}

// ============================================================
// gather_emb: per-graph sum of relu(Y1[r] + sum_in MSG) red-added into emb
// ============================================================
__global__ void gather_emb(const float4* __restrict__ Y1,
                           const float4* __restrict__ MSG,
                           const int* __restrict__ cnt, const int* __restrict__ csr,
                           int N, int rpg, float* __restrict__ emb, int colOff) {
    long long idx = (long long)blockIdx.x * blockDim.x + threadIdx.x;
    int row = (int)(idx >> 4);
    if (row >= N) return;
    int c = (int)(idx & 15);
    float4 acc = Y1[(size_t)row * 16 + c];
    float4 acc2 = make_float4(0.f, 0.f, 0.f, 0.f);
    int deg = cnt[row];
    const int* lst = csr + (size_t)row * MAXDEG;
    int e = 0;
    for (; e + 2 <= deg; e += 2) {
        float4 v0 = MSG[(size_t)lst[e] * 16 + c];
        float4 v1 = MSG[(size_t)lst[e + 1] * 16 + c];
        acc.x += v0.x; acc.y += v0.y; acc.z += v0.z; acc.w += v0.w;
        acc2.x += v1.x; acc2.y += v1.y; acc2.z += v1.z; acc2.w += v1.w;
    }
    if (e < deg) {
        float4 v = MSG[(size_t)lst[e] * 16 + c];
        acc.x += v.x; acc.y += v.y; acc.z += v.z; acc.w += v.w;
    }
    acc.x += acc2.x; acc.y += acc2.y; acc.z += acc2.z; acc.w += acc2.w;
    acc.x = fmaxf(acc.x, 0.f); acc.y = fmaxf(acc.y, 0.f);
    acc.z = fmaxf(acc.z, 0.f); acc.w = fmaxf(acc.w, 0.f);
    int g = row / rpg;
    red4(emb + (size_t)g * EMB_DIM + colOff + c * 4, acc);
}

// ============================================================
// tf32 mma.sync dual GEMM, split-K phased staging (R8/R10-verified).
// MODE 0: contiguous rows (KP == K), optional relu.
// MODE 2: [h[ia], h[ib]] + iso scalar; K=128, KP=64.
// MODE 3: [h[ia], h[ib], h[ic]] + iso one-hot; K=192, KP=96.
// ============================================================
template <int K, int KP, int MODE>
__global__ void __launch_bounds__(256)
gemm_mma(const float* __restrict__ X,
         const int* __restrict__ ia, const int* __restrict__ ib,
         const int* __restrict__ ic,
         const float* __restrict__ iso,
         const float* __restrict__ Wa, const float* __restrict__ Wb, int wK,
         float* __restrict__ Y1, float* __restrict__ MSG, int reluIn) {
    extern __shared__ float sm[];
    constexpr int SA  = KP + 4;
    constexpr int NPH = K / KP;
    float* As   = sm;                    // [128][SA]
    float* Bs   = sm + 128 * SA;         // [KP][136]
    float* isoT = Bs + KP * 136;         // MODE3: [128][4] ; MODE2: [128]

    const int t = threadIdx.x;
    const int rowBase = blockIdx.x * 128;

    const int lane = t & 31;
    const int wid = t >> 5;
    const int wm = (wid & 3) * 32;
    const int wn = (wid >> 2) * 64;
    const int ar = lane >> 2, ak = lane & 3;
    const int bc = lane >> 2, bk = lane & 3;

    float acc[2][8][4];
#pragma unroll
    for (int mt = 0; mt < 2; mt++)
#pragma unroll
        for (int nt = 0; nt < 8; nt++) {
            acc[mt][nt][0] = 0.f; acc[mt][nt][1] = 0.f;
            acc[mt][nt][2] = 0.f; acc[mt][nt][3] = 0.f;
        }

#pragma unroll
    for (int ph = 0; ph < NPH; ph++) {
        // ---- stage B phase (tf32). float4 only when wK % 4 == 0. ----
        {
            constexpr int K4 = KP / 4;
            const bool vec4 = ((wK & 3) == 0);
            for (int i = t; i < 128 * K4; i += 256) {
                int j = i / K4;
                int k = (i - j * K4) * 4;
                int gk = ph * KP + k;
                const float* src = (j < 64) ? (Wa + (size_t)j * wK)
                                            : (Wb + (size_t)(j - 64) * wK);
                float4 v;
                if (vec4) {
                    v = *(const float4*)(src + gk);
                } else {
                    v.x = src[gk]; v.y = src[gk + 1]; v.z = src[gk + 2]; v.w = src[gk + 3];
                }
                Bs[(k + 0) * 136 + j] = __uint_as_float(f2tf32(v.x));
                Bs[(k + 1) * 136 + j] = __uint_as_float(f2tf32(v.y));
                Bs[(k + 2) * 136 + j] = __uint_as_float(f2tf32(v.z));
                Bs[(k + 3) * 136 + j] = __uint_as_float(f2tf32(v.w));
            }
            if (ph == 0) {
                if (MODE == 3) {
                    for (int i = t; i < 512; i += 256) {
                        int j = i >> 2, e = i & 3;
                        const float* src = (j < 64) ? (Wa + (size_t)j * wK)
                                                    : (Wb + (size_t)(j - 64) * wK);
                        isoT[j * 4 + e] = src[K + e];
                    }
                } else if (MODE == 2) {
                    if (t < 128) {
                        const float* src = (t < 64) ? (Wa + (size_t)t * wK)
                                                    : (Wb + (size_t)(t - 64) * wK);
                        isoT[t] = src[K];
                    }
                }
            }
        }

        // ---- stage A phase (relu + tf32) ----
        if (MODE == 0) {
            constexpr int K4 = KP / 4;
            for (int i = t; i < 128 * K4; i += 256) {
                int row = i / K4;
                int k = (i - row * K4) * 4;
                float4 v = *(const float4*)(X + (size_t)(rowBase + row) * K + ph * KP + k);
                uint4 u;
                if (reluIn) {
                    u.x = f2tf32_relu(v.x); u.y = f2tf32_relu(v.y);
                    u.z = f2tf32_relu(v.z); u.w = f2tf32_relu(v.w);
                } else {
                    u.x = f2tf32(v.x); u.y = f2tf32(v.y);
                    u.z = f2tf32(v.z); u.w = f2tf32(v.w);
                }
                *(uint4*)(As + row * SA + k) = u;
            }
        } else if (MODE == 2) {
            const int r = t >> 1, half = t & 1;
            const int* idxp = (ph == 0) ? ia : ib;
            int srcRow = idxp[rowBase + r];
            const float4* src = (const float4*)(X + (size_t)srcRow * 64) + half * 8;
#pragma unroll
            for (int i = 0; i < 8; i++) {
                float4 v = src[i];
                uint4 u;
                u.x = f2tf32_relu(v.x); u.y = f2tf32_relu(v.y);
                u.z = f2tf32_relu(v.z); u.w = f2tf32_relu(v.w);
                *(uint4*)(As + r * SA + half * 32 + i * 4) = u;
            }
        } else {  // MODE 3, KP = 96
            const int r = t >> 1, half = t & 1;
#pragma unroll
            for (int c = 0; c < 12; c++) {
                int lk = half * 48 + c * 4;
                int gk = ph * KP + lk;
                int seg = gk >> 6;
                const int* idxp = (seg == 0) ? ia : (seg == 1) ? ib : ic;
                int srcRow = idxp[rowBase + r];
                float4 v = *(const float4*)(X + (size_t)srcRow * 64 + (gk & 63));
                uint4 u;
                u.x = f2tf32_relu(v.x); u.y = f2tf32_relu(v.y);
                u.z = f2tf32_relu(v.z); u.w = f2tf32_relu(v.w);
                *(uint4*)(As + r * SA + lk) = u;
            }
        }
        __syncthreads();

        // ---- compute over this phase ----
#pragma unroll 2
        for (int k0 = 0; k0 < KP; k0 += 8) {
            uint32_t af[2][4];
#pragma unroll
            for (int mt = 0; mt < 2; mt++) {
                const float* p = As + (wm + mt * 16 + ar) * SA + k0 + ak;
                af[mt][0] = __float_as_uint(p[0]);
                af[mt][1] = __float_as_uint(p[8 * SA]);
                af[mt][2] = __float_as_uint(p[4]);
                af[mt][3] = __float_as_uint(p[8 * SA + 4]);
            }
            uint32_t bf[8][2];
#pragma unroll
            for (int nt = 0; nt < 8; nt++) {
                const float* p = Bs + (k0 + bk) * 136 + wn + nt * 8 + bc;
                bf[nt][0] = __float_as_uint(p[0]);
                bf[nt][1] = __float_as_uint(p[4 * 136]);
            }
#pragma unroll
            for (int mt = 0; mt < 2; mt++)
#pragma unroll
                for (int nt = 0; nt < 8; nt++)
                    mma_tf32(acc[mt][nt], af[mt], bf[nt]);
        }
        if (ph + 1 < NPH) __syncthreads();
    }

    // ---- epilogue ----
    float* dstBase = (wid >> 2) ? MSG : Y1;
#pragma unroll
    for (int mt = 0; mt < 2; mt++) {
        int r0 = rowBase + wm + mt * 16 + (lane >> 2);
        int r1 = r0 + 8;
        int e0 = 0, e1 = 0;
        float s0 = 0.f, s1 = 0.f;
        if (MODE == 3) {
            float4 v0 = ((const float4*)iso)[r0];
            float4 v1 = ((const float4*)iso)[r1];
            e0 = (int)(v0.y + 2.f * v0.z + 3.f * v0.w + 0.5f);
            e1 = (int)(v1.y + 2.f * v1.z + 3.f * v1.w + 0.5f);
        } else if (MODE == 2) {
            s0 = iso[r0];
            s1 = iso[r1];
        }
        float* d0 = dstBase + (size_t)r0 * 64;
        float* d1 = dstBase + (size_t)r1 * 64;
#pragma unroll
        for (int nt = 0; nt < 8; nt++) {
            int gc = wn + nt * 8 + 2 * (lane & 3);
            int oc = gc & 63;
            float v0 = acc[mt][nt][0], v1 = acc[mt][nt][1];
            float v2 = acc[mt][nt][2], v3 = acc[mt][nt][3];
            if (MODE == 3) {
                v0 += isoT[gc * 4 + e0];       v1 += isoT[(gc + 1) * 4 + e0];
                v2 += isoT[gc * 4 + e1];       v3 += isoT[(gc + 1) * 4 + e1];
            } else if (MODE == 2) {
                v0 += s0 * isoT[gc];           v1 += s0 * isoT[gc + 1];
                v2 += s1 * isoT[gc];           v3 += s1 * isoT[gc + 1];
            }
            *(float2*)(d0 + oc) = make_float2(v0, v1);
            *(float2*)(d1 + oc) = make_float2(v2, v3);
        }
    }
}

// ============================================================
// FFMA path (level 1) — R10-verified
// ============================================================
template <int KPAD>
__global__ void __launch_bounds__(256)
gemm_dual(const float* __restrict__ Xsrc,
          const float* __restrict__ Wt,
          float* __restrict__ Y1, float* __restrict__ MSG,
          int reluIn) {
    extern __shared__ float smf[];
    float* Xs  = smf;
    float* Wsh = smf + 64 * KPAD;
    const int t = threadIdx.x;
    const int rowBase = blockIdx.x * 64;

    {
        const float4* src = (const float4*)(Xsrc + (size_t)rowBase * KPAD);
        float4* dst = (float4*)Xs;
        const int n4 = 64 * KPAD / 4;
        for (int i = t; i < n4; i += 256) {
            float4 v = src[i];
            if (reluIn) {
                v.x = fmaxf(v.x, 0.f); v.y = fmaxf(v.y, 0.f);
                v.z = fmaxf(v.z, 0.f); v.w = fmaxf(v.w, 0.f);
            }
            dst[i] = v;
        }
    }

    const int cg = t & 31;
    const int rg = t >> 5;
    float acc[8][4];
#pragma unroll
    for (int r = 0; r < 8; r++) {
        acc[r][0] = acc[r][1] = acc[r][2] = acc[r][3] = 0.f;
    }
    const float* Xw = Xs + rg * 8 * KPAD;

    for (int k0 = 0; k0 < KPAD; k0 += 32) {
        __syncthreads();
        {
            const float4* s4 = (const float4*)(Wt + (size_t)k0 * 128);
            float4* d4 = (float4*)Wsh;
#pragma unroll
            for (int i = 0; i < 4; i++) d4[t + i * 256] = s4[t + i * 256];
        }
        __syncthreads();
#pragma unroll
        for (int kk = 0; kk < 32; kk++) {
            float4 wv = *(const float4*)(Wsh + kk * 128 + cg * 4);
#pragma unroll
            for (int r = 0; r < 8; r++) {
                float xv = Xw[r * KPAD + k0 + kk];
                acc[r][0] += xv * wv.x;
                acc[r][1] += xv * wv.y;
                acc[r][2] += xv * wv.z;
                acc[r][3] += xv * wv.w;
            }
        }
    }

    float* outp = (cg < 16)
        ? (Y1  + (size_t)(rowBase + rg * 8) * 64 + cg * 4)
        : (MSG + (size_t)(rowBase + rg * 8) * 64 + (cg - 16) * 4);
#pragma unroll
    for (int r = 0; r < 8; r++) {
        float4 v;
        v.x = acc[r][0]; v.y = acc[r][1]; v.z = acc[r][2]; v.w = acc[r][3];
        *(float4*)(outp + (size_t)r * 64) = v;
    }
}

// ---------------- scatter (level 1 only; tiny edge set) ----------------
__global__ void scatter_add(const float4* __restrict__ msg,
                            const int* __restrict__ src,
                            const int* __restrict__ dst,
                            int E, float* __restrict__ out) {
    long long idx = (long long)blockIdx.x * blockDim.x + threadIdx.x;
    int e = (int)(idx >> 4);
    if (e >= E) return;
    int c = (int)(idx & 15);
    float4 v = msg[(size_t)src[e] * 16 + c];
    float* o = out + (size_t)dst[e] * 64 + c * 4;
    red4(o, v);
}

// ---------------- level-1 per-graph column sum with fused relu ----------------
__global__ void seg_reduce(const float* __restrict__ Y, int rpg,
                           float* __restrict__ emb, int colOff) {
    __shared__ float partial[4][64];
    int g = blockIdx.x;
    int c = threadIdx.x & 63;
    int s = threadIdx.x >> 6;
    const float* base = Y + (size_t)g * rpg * 64 + c;
    float sum = 0.f;
    for (int i = s; i < rpg; i += 4) sum += fmaxf(base[(size_t)i * 64], 0.f);
    partial[s][c] = sum;
    __syncthreads();
    if (s == 0)
        emb[g * EMB_DIM + colOff + c] =
            partial[0][c] + partial[1][c] + partial[2][c] + partial[3][c];
}

// ---------------- classifier head ----------------
__global__ void head(const float* __restrict__ emb,
                     const float* __restrict__ cW1, const float* __restrict__ cb1,
                     const float* __restrict__ cW2, const float* __restrict__ cb2,
                     float* __restrict__ out) {
    __shared__ float e[EMB_DIM];
    __shared__ float hid[H];
    int g = blockIdx.x;
    int t = threadIdx.x;
    for (int k = t; k < EMB_DIM; k += H) e[k] = emb[g * EMB_DIM + k];
    __syncthreads();
    float a = cb1[t];
    const float* w = cW1 + t * EMB_DIM;
#pragma unroll 4
    for (int k = 0; k < EMB_DIM; k++) a += e[k] * w[k];
    hid[t] = fmaxf(a, 0.f);
    __syncthreads();
    if (t < OUT_DIM) {
        float a2 = cb2[t];
        const float* w2 = cW2 + t * H;
#pragma unroll 8
        for (int k = 0; k < H; k++) a2 += hid[k] * w2[k];
        out[g * OUT_DIM + t] = a2;
    }
}

// ---------------- launch ----------------
extern "C" void kernel_launch(void* const* d_in, const int* in_sizes, int n_in,
                              void* d_out, int out_size) {
    const float* x           = (const float*)d_in[0];
    const int*   edge_index  = (const int*)d_in[1];
    const int*   gu2         = (const int*)d_in[3];
    const int*   gv2         = (const int*)d_in[4];
    const float* iso2        = (const float*)d_in[5];
    const int*   two_edges   = (const int*)d_in[6];
    const int*   ga3         = (const int*)d_in[8];
    const int*   gb3         = (const int*)d_in[9];
    const int*   gc3         = (const int*)d_in[10];
    const float* iso3        = (const float*)d_in[11];
    const int*   three_edges = (const int*)d_in[12];
    const float* g1W1_0 = (const float*)d_in[14];
    const float* g1W2_0 = (const float*)d_in[15];
    const float* g1W1_1 = (const float*)d_in[16];
    const float* g1W2_1 = (const float*)d_in[17];
    const float* g1W1_2 = (const float*)d_in[18];
    const float* g1W2_2 = (const float*)d_in[19];
    const float* g2W1_0 = (const float*)d_in[20];
    const float* g2W2_0 = (const float*)d_in[21];
    const float* g2W1_1 = (const float*)d_in[22];
    const float* g2W2_1 = (const float*)d_in[23];
    const float* g3W1_0 = (const float*)d_in[24];
    const float* g3W2_0 = (const float*)d_in[25];
    const float* g3W1_1 = (const float*)d_in[26];
    const float* g3W2_1 = (const float*)d_in[27];
    const float* cW1    = (const float*)d_in[28];
    const float* cb1    = (const float*)d_in[29];
    const float* cW2    = (const float*)d_in[30];
    const float* cb2    = (const float*)d_in[31];
    float* out = (float*)d_out;

    const int E1 = in_sizes[1] / 2;
    const int E2 = in_sizes[6] / 2;
    const int E3 = in_sizes[12] / 2;

    float *hA, *hB, *msg1, *y2, *msg2, *h2, *y3, *msg3, *h3, *emb, *Wt;
    int *cnt2, *csr2, *cnt3, *csr3;
    cudaGetSymbolAddress((void**)&hA,   d_hA);
    cudaGetSymbolAddress((void**)&hB,   d_hB);
    cudaGetSymbolAddress((void**)&msg1, d_msg1);
    cudaGetSymbolAddress((void**)&y2,   d_y2);
    cudaGetSymbolAddress((void**)&msg2, d_msg2);
    cudaGetSymbolAddress((void**)&h2,   d_h2);
    cudaGetSymbolAddress((void**)&y3,   d_y3);
    cudaGetSymbolAddress((void**)&msg3, d_msg3);
    cudaGetSymbolAddress((void**)&h3,   d_h3);
    cudaGetSymbolAddress((void**)&emb,  d_emb);
    cudaGetSymbolAddress((void**)&Wt,   d_Wt);
    cudaGetSymbolAddress((void**)&cnt2, d_cnt2);
    cudaGetSymbolAddress((void**)&csr2, d_csr2);
    cudaGetSymbolAddress((void**)&cnt3, d_cnt3);
    cudaGetSymbolAddress((void**)&csr3, d_csr3);

    // dynamic smem opt-in
    const int SM_K192 = (128 * 100 + 96 * 136 + 512) * 4;   // 105472 -> 2 CTAs/SM
    const int SM_K128 = (128 * 68  + 64 * 136 + 128) * 4;   // 70144
    const int SM_K64  = (128 * 68  + 64 * 136) * 4;         // 69632
    cudaFuncSetAttribute((const void*)gemm_mma<192, 96, 3>,
                         cudaFuncAttributeMaxDynamicSharedMemorySize, SM_K192);
    cudaFuncSetAttribute((const void*)gemm_mma<128, 64, 2>,
                         cudaFuncAttributeMaxDynamicSharedMemorySize, SM_K128);
    cudaFuncSetAttribute((const void*)gemm_mma<64, 64, 0>,
                         cudaFuncAttributeMaxDynamicSharedMemorySize, SM_K64);

    // ---- prep: one kernel for zeros + weight transpose, one for both CSRs ----
    WPrepAll P;
    P.w1[0] = g1W1_0; P.w2[0] = g1W2_0; P.K[0] = 32; P.off[0] = 0;
    P.w1[1] = g1W1_1; P.w2[1] = g1W2_1; P.K[1] = 64; P.off[1] = 32;
    P.w1[2] = g1W1_2; P.w2[2] = g1W2_2; P.K[2] = 64; P.off[2] = 96;
    prep_all<<<ZB3 + 4, 256>>>(P, Wt, cnt2, cnt3, emb);

    const int blocks2 = (E2 + 1023) / 1024;
    const int blocks3 = (E3 + 1023) / 1024;
    csr_fill2<<<blocks2 + blocks3, 256>>>(two_edges + E2, two_edges, E2, cnt2, csr2,
                                          three_edges + E3, three_edges, E3, cnt3, csr3,
                                          blocks2);

    const int* e1s = edge_index;  const int* e1d = edge_index + E1;
    auto sc_grid = [](int E) { return (int)(((long long)E * 16 + 255) / 256); };
    auto ga_grid = [](int N) { return (int)(((long long)N * 16 + 255) / 256); };

    const size_t sm32 = (64 * 32 + 32 * 128) * 4;
    const size_t sm64 = (64 * 64 + 32 * 128) * 4;

    // ---- level 1 (3 layers, exact FFMA); hA holds PRE-activation ----
    gemm_dual<32><<<NNODES / 64, 256, sm32>>>(x, Wt + 0 * 128, hA, msg1, 0);
    scatter_add<<<sc_grid(E1), 256>>>((const float4*)msg1, e1s, e1d, E1, hA);

    gemm_dual<64><<<NNODES / 64, 256, sm64>>>(hA, Wt + 32 * 128, hB, msg1, 1);
    scatter_add<<<sc_grid(E1), 256>>>((const float4*)msg1, e1s, e1d, E1, hB);

    gemm_dual<64><<<NNODES / 64, 256, sm64>>>(hB, Wt + 96 * 128, hA, msg1, 1);
    scatter_add<<<sc_grid(E1), 256>>>((const float4*)msg1, e1s, e1d, E1, hA);

    seg_reduce<<<GG, 256>>>(hA, NPER, emb, 0);

    // ---- level 2 (2 layers, tf32 mma + gathers) ----
    gemm_mma<128, 64, 2><<<N2 / 128, 256, SM_K128>>>(hA, gu2, gv2, nullptr, iso2,
                                                     g2W1_0, g2W2_0, 129,
                                                     y2, msg2, 1);
    gather_add<<<ga_grid(N2), 256>>>((const float4*)y2, (const float4*)msg2,
                                     cnt2, csr2, N2, (float4*)h2);

    gemm_mma<64, 64, 0><<<N2 / 128, 256, SM_K64>>>(h2, nullptr, nullptr, nullptr, nullptr,
                                                   g2W1_1, g2W2_1, 64,
                                                   y2, msg2, 1);
    gather_emb<<<ga_grid(N2), 256>>>((const float4*)y2, (const float4*)msg2,
                                     cnt2, csr2, N2, P2, emb, H);

    // ---- level 3 (2 layers, tf32 mma + gathers) ----
    gemm_mma<192, 96, 3><<<N3 / 128, 256, SM_K192>>>(hA, ga3, gb3, gc3, iso3,
                                                     g3W1_0, g3W2_0, 196,
                                                     y3, msg3, 1);
    gather_add<<<ga_grid(N3), 256>>>((const float4*)y3, (const float4*)msg3,
                                     cnt3, csr3, N3, (float4*)h3);

    gemm_mma<64, 64, 0><<<N3 / 128, 256, SM_K64>>>(h3, nullptr, nullptr, nullptr, nullptr,
                                                   g3W1_1, g3W2_1, 64,
                                                   y3, msg3, 1);
    gather_emb<<<ga_grid(N3), 256>>>((const float4*)y3, (const float4*)msg3,
                                     cnt3, csr3, N3, P3, emb, 2 * H);

    // ---- head ----
    head<<<GG, H>>>(emb, cW1, cb1, cW2, cb2, out);
}

// round 14
// speedup vs baseline: 1.1120x; 1.0698x over previous
#include <cuda_runtime.h>
#include <cstdint>

// Problem constants (fixed by reference _build_structures with seed 0)
#define GG       128
#define NPER     20
#define NNODES   (GG * NPER)          // 2560
#define P2       190
#define N2       (GG * P2)            // 24320
#define P3       1140
#define N3       (GG * P3)            // 145920
#define H        64
#define EMB_DIM  192
#define OUT_DIM  10
#define MAXDEG   64                   // in-degree bound: <= 3*(NPER-3) = 51

// -------- scratch (static device globals; no runtime allocation) --------
__device__ float d_hA[NNODES * H];
__device__ float d_hB[NNODES * H];
__device__ float d_msg1[NNODES * H];

__device__ float d_y2[N2 * H];
__device__ float d_msg2[N2 * H];
__device__ float d_h2[N2 * H];

__device__ float d_y3[N3 * H];
__device__ float d_msg3[N3 * H];
__device__ float d_h3[N3 * H];

__device__ float d_emb[GG * EMB_DIM];
__device__ float d_Wt[160 * 128];

__device__ int   d_cnt2[N2];
__device__ int   d_csr2[N2 * MAXDEG];
__device__ int   d_cnt3[N3];
__device__ int   d_csr3[N3 * MAXDEG];

// ============================================================
// helpers
// ============================================================
__device__ __forceinline__ uint32_t f2tf32(float f) {
    uint32_t u;
    asm("cvt.rna.tf32.f32 %0, %1;" : "=r"(u) : "f"(f));
    return u;
}
__device__ __forceinline__ uint32_t f2tf32_relu(float f) {
    return f2tf32(fmaxf(f, 0.f));
}
__device__ __forceinline__ void mma_tf32(float* c, const uint32_t* a, const uint32_t* b) {
    asm volatile(
        "mma.sync.aligned.m16n8k8.row.col.f32.tf32.tf32.f32 "
        "{%0,%1,%2,%3}, {%4,%5,%6,%7}, {%8,%9}, {%0,%1,%2,%3};"
        : "+f"(c[0]), "+f"(c[1]), "+f"(c[2]), "+f"(c[3])
        : "r"(a[0]), "r"(a[1]), "r"(a[2]), "r"(a[3]), "r"(b[0]), "r"(b[1]));
}
__device__ __forceinline__ void red4(float* p, float4 v) {
    asm volatile("red.global.add.v4.f32 [%0], {%1,%2,%3,%4};"
                 :: "l"(p), "f"(v.x), "f"(v.y), "f"(v.z), "f"(v.w) : "memory");
}

// ============================================================
// prep_all: one launch zeroing cnt2/cnt3/emb AND transposing the 3
// level-1 weight pairs into Wt.
// ============================================================
#define ZB2 12
#define ZB3 (ZB2 + 72)
struct WPrepAll {
    const float* w1[3];
    const float* w2[3];
    int K[3];
    int off[3];
};

__global__ void prep_all(WPrepAll P, float* __restrict__ Wt,
                         int* __restrict__ cnt2, int* __restrict__ cnt3,
                         float* __restrict__ emb) {
    int b = blockIdx.x;
    int t = threadIdx.x;
    if (b < ZB2) {
        for (int i = b * 256 + t; i < N2; i += ZB2 * 256) cnt2[i] = 0;
    } else if (b < ZB3) {
        int bb = b - ZB2;
        for (int i = bb * 256 + t; i < N3; i += (ZB3 - ZB2) * 256) cnt3[i] = 0;
    } else if (b == ZB3) {
        for (int i = t; i < GG * EMB_DIM; i += 256) emb[i] = 0.f;
    } else {
        int l = b - ZB3 - 1;   // 0..2
        const float* __restrict__ w1 = P.w1[l];
        const float* __restrict__ w2 = P.w2[l];
        int K = P.K[l];
        float* out = Wt + (size_t)P.off[l] * 128;
        for (int i = t; i < K * 128; i += 256) {
            int k = i >> 7, j = i & 127;
            out[i] = (j < 64) ? w1[j * K + k] : w2[(j - 64) * K + k];
        }
    }
}

// ============================================================
// merged CSR-by-dst build for levels 2 and 3; 4 edges per thread (MLP)
// ============================================================
__global__ void csr_fill2(const int* __restrict__ key2, const int* __restrict__ val2,
                          int E2v, int* __restrict__ cnt2v, int* __restrict__ csr2v,
                          const int* __restrict__ key3, const int* __restrict__ val3,
                          int E3v, int* __restrict__ cnt3v, int* __restrict__ csr3v,
                          int blocks2) {
    const int b = blockIdx.x;
    const int* __restrict__ key;
    const int* __restrict__ val;
    int* __restrict__ cnt;
    int* __restrict__ csr;
    int E, base;
    if (b < blocks2) {
        key = key2; val = val2; cnt = cnt2v; csr = csr2v; E = E2v;
        base = (b * 256 + threadIdx.x) * 4;
    } else {
        key = key3; val = val3; cnt = cnt3v; csr = csr3v; E = E3v;
        base = ((b - blocks2) * 256 + threadIdx.x) * 4;
    }
    if (base >= E) return;
    int n = min(4, E - base);
    int ks[4], vs[4];
#pragma unroll
    for (int i = 0; i < 4; i++) {
        if (i < n) { ks[i] = key[base + i]; vs[i] = val[base + i]; }
    }
#pragma unroll
    for (int i = 0; i < 4; i++) {
        if (i < n) {
            int slot = atomicAdd(&cnt[ks[i]], 1);
            csr[(size_t)ks[i] * MAXDEG + slot] = vs[i];
        }
    }
}

// ============================================================
// gather_add: OUT[r] = Y1[r] + sum_{s in in(r)} MSG[s]  (16 thr/row, 2x unroll)
// ============================================================
__global__ void gather_add(const float4* __restrict__ Y1,
                           const float4* __restrict__ MSG,
                           const int* __restrict__ cnt, const int* __restrict__ csr,
                           int N, float4* __restrict__ OUT) {
    long long idx = (long long)blockIdx.x * blockDim.x + threadIdx.x;
    int row = (int)(idx >> 4);
    if (row >= N) return;
    int c = (int)(idx & 15);
    float4 acc = Y1[(size_t)row * 16 + c];
    float4 acc2 = make_float4(0.f, 0.f, 0.f, 0.f);
    int deg = cnt[row];
    const int* lst = csr + (size_t)row * MAXDEG;
    int e = 0;
    for (; e + 2 <= deg; e += 2) {
        float4 v0 = MSG[(size_t)lst[e] * 16 + c];
        float4 v1 = MSG[(size_t)lst[e + 1] * 16 + c];
        acc.x += v0.x; acc.y += v0.y; acc.z += v0.z; acc.w += v0.w;
        acc2.x += v1.x; acc2.y += v1.y; acc2.z += v1.z; acc2.w += v1.w;
    }
    if (e < deg) {
        float4 v = MSG[(size_t)lst[e] * 16 + c];
        acc.x += v.x; acc.y += v.y; acc.z += v.z; acc.w += v.w;
    }
    acc.x += acc2.x; acc.y += acc2.y; acc.z += acc2.z; acc.w += acc2.w;
    OUT[(size_t)row * 16 + c] = acc;
}

// ============================================================
// gather_emb: per-graph sum of relu(Y1[r] + sum_in MSG) red-added into emb
// ============================================================
__global__ void gather_emb(const float4* __restrict__ Y1,
                           const float4* __restrict__ MSG,
                           const int* __restrict__ cnt, const int* __restrict__ csr,
                           int N, int rpg, float* __restrict__ emb, int colOff) {
    long long idx = (long long)blockIdx.x * blockDim.x + threadIdx.x;
    int row = (int)(idx >> 4);
    if (row >= N) return;
    int c = (int)(idx & 15);
    float4 acc = Y1[(size_t)row * 16 + c];
    float4 acc2 = make_float4(0.f, 0.f, 0.f, 0.f);
    int deg = cnt[row];
    const int* lst = csr + (size_t)row * MAXDEG;
    int e = 0;
    for (; e + 2 <= deg; e += 2) {
        float4 v0 = MSG[(size_t)lst[e] * 16 + c];
        float4 v1 = MSG[(size_t)lst[e + 1] * 16 + c];
        acc.x += v0.x; acc.y += v0.y; acc.z += v0.z; acc.w += v0.w;
        acc2.x += v1.x; acc2.y += v1.y; acc2.z += v1.z; acc2.w += v1.w;
    }
    if (e < deg) {
        float4 v = MSG[(size_t)lst[e] * 16 + c];
        acc.x += v.x; acc.y += v.y; acc.z += v.z; acc.w += v.w;
    }
    acc.x += acc2.x; acc.y += acc2.y; acc.z += acc2.z; acc.w += acc2.w;
    acc.x = fmaxf(acc.x, 0.f); acc.y = fmaxf(acc.y, 0.f);
    acc.z = fmaxf(acc.z, 0.f); acc.w = fmaxf(acc.w, 0.f);
    int g = row / rpg;
    red4(emb + (size_t)g * EMB_DIM + colOff + c * 4, acc);
}

// ============================================================
// tf32 mma.sync dual GEMM, split-K phased staging (R8/R10-verified).
// MODE 0: contiguous rows (KP == K), optional relu.
// MODE 2: [h[ia], h[ib]] + iso scalar; K=128, KP=64.
// MODE 3: [h[ia], h[ib], h[ic]] + iso one-hot; K=192, KP=96.
// ============================================================
template <int K, int KP, int MODE>
__global__ void __launch_bounds__(256)
gemm_mma(const float* __restrict__ X,
         const int* __restrict__ ia, const int* __restrict__ ib,
         const int* __restrict__ ic,
         const float* __restrict__ iso,
         const float* __restrict__ Wa, const float* __restrict__ Wb, int wK,
         float* __restrict__ Y1, float* __restrict__ MSG, int reluIn) {
    extern __shared__ float sm[];
    constexpr int SA  = KP + 4;
    constexpr int NPH = K / KP;
    float* As   = sm;                    // [128][SA]
    float* Bs   = sm + 128 * SA;         // [KP][136]
    float* isoT = Bs + KP * 136;         // MODE3: [128][4] ; MODE2: [128]

    const int t = threadIdx.x;
    const int rowBase = blockIdx.x * 128;

    const int lane = t & 31;
    const int wid = t >> 5;
    const int wm = (wid & 3) * 32;
    const int wn = (wid >> 2) * 64;
    const int ar = lane >> 2, ak = lane & 3;
    const int bc = lane >> 2, bk = lane & 3;

    float acc[2][8][4];
#pragma unroll
    for (int mt = 0; mt < 2; mt++)
#pragma unroll
        for (int nt = 0; nt < 8; nt++) {
            acc[mt][nt][0] = 0.f; acc[mt][nt][1] = 0.f;
            acc[mt][nt][2] = 0.f; acc[mt][nt][3] = 0.f;
        }

#pragma unroll
    for (int ph = 0; ph < NPH; ph++) {
        // ---- stage B phase (tf32). float4 only when wK % 4 == 0. ----
        {
            constexpr int K4 = KP / 4;
            const bool vec4 = ((wK & 3) == 0);
            for (int i = t; i < 128 * K4; i += 256) {
                int j = i / K4;
                int k = (i - j * K4) * 4;
                int gk = ph * KP + k;
                const float* src = (j < 64) ? (Wa + (size_t)j * wK)
                                            : (Wb + (size_t)(j - 64) * wK);
                float4 v;
                if (vec4) {
                    v = *(const float4*)(src + gk);
                } else {
                    v.x = src[gk]; v.y = src[gk + 1]; v.z = src[gk + 2]; v.w = src[gk + 3];
                }
                Bs[(k + 0) * 136 + j] = __uint_as_float(f2tf32(v.x));
                Bs[(k + 1) * 136 + j] = __uint_as_float(f2tf32(v.y));
                Bs[(k + 2) * 136 + j] = __uint_as_float(f2tf32(v.z));
                Bs[(k + 3) * 136 + j] = __uint_as_float(f2tf32(v.w));
            }
            if (ph == 0) {
                if (MODE == 3) {
                    for (int i = t; i < 512; i += 256) {
                        int j = i >> 2, e = i & 3;
                        const float* src = (j < 64) ? (Wa + (size_t)j * wK)
                                                    : (Wb + (size_t)(j - 64) * wK);
                        isoT[j * 4 + e] = src[K + e];
                    }
                } else if (MODE == 2) {
                    if (t < 128) {
                        const float* src = (t < 64) ? (Wa + (size_t)t * wK)
                                                    : (Wb + (size_t)(t - 64) * wK);
                        isoT[t] = src[K];
                    }
                }
            }
        }

        // ---- stage A phase (relu + tf32) ----
        if (MODE == 0) {
            constexpr int K4 = KP / 4;
            for (int i = t; i < 128 * K4; i += 256) {
                int row = i / K4;
                int k = (i - row * K4) * 4;
                float4 v = *(const float4*)(X + (size_t)(rowBase + row) * K + ph * KP + k);
                uint4 u;
                if (reluIn) {
                    u.x = f2tf32_relu(v.x); u.y = f2tf32_relu(v.y);
                    u.z = f2tf32_relu(v.z); u.w = f2tf32_relu(v.w);
                } else {
                    u.x = f2tf32(v.x); u.y = f2tf32(v.y);
                    u.z = f2tf32(v.z); u.w = f2tf32(v.w);
                }
                *(uint4*)(As + row * SA + k) = u;
            }
        } else if (MODE == 2) {
            const int r = t >> 1, half = t & 1;
            const int* idxp = (ph == 0) ? ia : ib;
            int srcRow = idxp[rowBase + r];
            const float4* src = (const float4*)(X + (size_t)srcRow * 64) + half * 8;
#pragma unroll
            for (int i = 0; i < 8; i++) {
                float4 v = src[i];
                uint4 u;
                u.x = f2tf32_relu(v.x); u.y = f2tf32_relu(v.y);
                u.z = f2tf32_relu(v.z); u.w = f2tf32_relu(v.w);
                *(uint4*)(As + r * SA + half * 32 + i * 4) = u;
            }
        } else {  // MODE 3, KP = 96
            const int r = t >> 1, half = t & 1;
#pragma unroll
            for (int c = 0; c < 12; c++) {
                int lk = half * 48 + c * 4;
                int gk = ph * KP + lk;
                int seg = gk >> 6;
                const int* idxp = (seg == 0) ? ia : (seg == 1) ? ib : ic;
                int srcRow = idxp[rowBase + r];
                float4 v = *(const float4*)(X + (size_t)srcRow * 64 + (gk & 63));
                uint4 u;
                u.x = f2tf32_relu(v.x); u.y = f2tf32_relu(v.y);
                u.z = f2tf32_relu(v.z); u.w = f2tf32_relu(v.w);
                *(uint4*)(As + r * SA + lk) = u;
            }
        }
        __syncthreads();

        // ---- compute over this phase ----
#pragma unroll 2
        for (int k0 = 0; k0 < KP; k0 += 8) {
            uint32_t af[2][4];
#pragma unroll
            for (int mt = 0; mt < 2; mt++) {
                const float* p = As + (wm + mt * 16 + ar) * SA + k0 + ak;
                af[mt][0] = __float_as_uint(p[0]);
                af[mt][1] = __float_as_uint(p[8 * SA]);
                af[mt][2] = __float_as_uint(p[4]);
                af[mt][3] = __float_as_uint(p[8 * SA + 4]);
            }
            uint32_t bf[8][2];
#pragma unroll
            for (int nt = 0; nt < 8; nt++) {
                const float* p = Bs + (k0 + bk) * 136 + wn + nt * 8 + bc;
                bf[nt][0] = __float_as_uint(p[0]);
                bf[nt][1] = __float_as_uint(p[4 * 136]);
            }
#pragma unroll
            for (int mt = 0; mt < 2; mt++)
#pragma unroll
                for (int nt = 0; nt < 8; nt++)
                    mma_tf32(acc[mt][nt], af[mt], bf[nt]);
        }
        if (ph + 1 < NPH) __syncthreads();
    }

    // ---- epilogue ----
    float* dstBase = (wid >> 2) ? MSG : Y1;
#pragma unroll
    for (int mt = 0; mt < 2; mt++) {
        int r0 = rowBase + wm + mt * 16 + (lane >> 2);
        int r1 = r0 + 8;
        int e0 = 0, e1 = 0;
        float s0 = 0.f, s1 = 0.f;
        if (MODE == 3) {
            float4 v0 = ((const float4*)iso)[r0];
            float4 v1 = ((const float4*)iso)[r1];
            e0 = (int)(v0.y + 2.f * v0.z + 3.f * v0.w + 0.5f);
            e1 = (int)(v1.y + 2.f * v1.z + 3.f * v1.w + 0.5f);
        } else if (MODE == 2) {
            s0 = iso[r0];
            s1 = iso[r1];
        }
        float* d0 = dstBase + (size_t)r0 * 64;
        float* d1 = dstBase + (size_t)r1 * 64;
#pragma unroll
        for (int nt = 0; nt < 8; nt++) {
            int gc = wn + nt * 8 + 2 * (lane & 3);
            int oc = gc & 63;
            float v0 = acc[mt][nt][0], v1 = acc[mt][nt][1];
            float v2 = acc[mt][nt][2], v3 = acc[mt][nt][3];
            if (MODE == 3) {
                v0 += isoT[gc * 4 + e0];       v1 += isoT[(gc + 1) * 4 + e0];
                v2 += isoT[gc * 4 + e1];       v3 += isoT[(gc + 1) * 4 + e1];
            } else if (MODE == 2) {
                v0 += s0 * isoT[gc];           v1 += s0 * isoT[gc + 1];
                v2 += s1 * isoT[gc];           v3 += s1 * isoT[gc + 1];
            }
            *(float2*)(d0 + oc) = make_float2(v0, v1);
            *(float2*)(d1 + oc) = make_float2(v2, v3);
        }
    }
}

// ============================================================
// FFMA path (level 1) — R10-verified
// ============================================================
template <int KPAD>
__global__ void __launch_bounds__(256)
gemm_dual(const float* __restrict__ Xsrc,
          const float* __restrict__ Wt,
          float* __restrict__ Y1, float* __restrict__ MSG,
          int reluIn) {
    extern __shared__ float smf[];
    float* Xs  = smf;
    float* Wsh = smf + 64 * KPAD;
    const int t = threadIdx.x;
    const int rowBase = blockIdx.x * 64;

    {
        const float4* src = (const float4*)(Xsrc + (size_t)rowBase * KPAD);
        float4* dst = (float4*)Xs;
        const int n4 = 64 * KPAD / 4;
        for (int i = t; i < n4; i += 256) {
            float4 v = src[i];
            if (reluIn) {
                v.x = fmaxf(v.x, 0.f); v.y = fmaxf(v.y, 0.f);
                v.z = fmaxf(v.z, 0.f); v.w = fmaxf(v.w, 0.f);
            }
            dst[i] = v;
        }
    }

    const int cg = t & 31;
    const int rg = t >> 5;
    float acc[8][4];
#pragma unroll
    for (int r = 0; r < 8; r++) {
        acc[r][0] = acc[r][1] = acc[r][2] = acc[r][3] = 0.f;
    }
    const float* Xw = Xs + rg * 8 * KPAD;

    for (int k0 = 0; k0 < KPAD; k0 += 32) {
        __syncthreads();
        {
            const float4* s4 = (const float4*)(Wt + (size_t)k0 * 128);
            float4* d4 = (float4*)Wsh;
#pragma unroll
            for (int i = 0; i < 4; i++) d4[t + i * 256] = s4[t + i * 256];
        }
        __syncthreads();
#pragma unroll
        for (int kk = 0; kk < 32; kk++) {
            float4 wv = *(const float4*)(Wsh + kk * 128 + cg * 4);
#pragma unroll
            for (int r = 0; r < 8; r++) {
                float xv = Xw[r * KPAD + k0 + kk];
                acc[r][0] += xv * wv.x;
                acc[r][1] += xv * wv.y;
                acc[r][2] += xv * wv.z;
                acc[r][3] += xv * wv.w;
            }
        }
    }

    float* outp = (cg < 16)
        ? (Y1  + (size_t)(rowBase + rg * 8) * 64 + cg * 4)
        : (MSG + (size_t)(rowBase + rg * 8) * 64 + (cg - 16) * 4);
#pragma unroll
    for (int r = 0; r < 8; r++) {
        float4 v;
        v.x = acc[r][0]; v.y = acc[r][1]; v.z = acc[r][2]; v.w = acc[r][3];
        *(float4*)(outp + (size_t)r * 64) = v;
    }
}

// ---------------- scatter (level 1 only; tiny edge set) ----------------
__global__ void scatter_add(const float4* __restrict__ msg,
                            const int* __restrict__ src,
                            const int* __restrict__ dst,
                            int E, float* __restrict__ out) {
    long long idx = (long long)blockIdx.x * blockDim.x + threadIdx.x;
    int e = (int)(idx >> 4);
    if (e >= E) return;
    int c = (int)(idx & 15);
    float4 v = msg[(size_t)src[e] * 16 + c];
    float* o = out + (size_t)dst[e] * 64 + c * 4;
    red4(o, v);
}

// ---------------- level-1 per-graph column sum with fused relu ----------------
__global__ void seg_reduce(const float* __restrict__ Y, int rpg,
                           float* __restrict__ emb, int colOff) {
    __shared__ float partial[4][64];
    int g = blockIdx.x;
    int c = threadIdx.x & 63;
    int s = threadIdx.x >> 6;
    const float* base = Y + (size_t)g * rpg * 64 + c;
    float sum = 0.f;
    for (int i = s; i < rpg; i += 4) sum += fmaxf(base[(size_t)i * 64], 0.f);
    partial[s][c] = sum;
    __syncthreads();
    if (s == 0)
        emb[g * EMB_DIM + colOff + c] =
            partial[0][c] + partial[1][c] + partial[2][c] + partial[3][c];
}

// ---------------- classifier head ----------------
__global__ void head(const float* __restrict__ emb,
                     const float* __restrict__ cW1, const float* __restrict__ cb1,
                     const float* __restrict__ cW2, const float* __restrict__ cb2,
                     float* __restrict__ out) {
    __shared__ float e[EMB_DIM];
    __shared__ float hid[H];
    int g = blockIdx.x;
    int t = threadIdx.x;
    for (int k = t; k < EMB_DIM; k += H) e[k] = emb[g * EMB_DIM + k];
    __syncthreads();
    float a = cb1[t];
    const float* w = cW1 + t * EMB_DIM;
#pragma unroll 4
    for (int k = 0; k < EMB_DIM; k++) a += e[k] * w[k];
    hid[t] = fmaxf(a, 0.f);
    __syncthreads();
    if (t < OUT_DIM) {
        float a2 = cb2[t];
        const float* w2 = cW2 + t * H;
#pragma unroll 8
        for (int k = 0; k < H; k++) a2 += hid[k] * w2[k];
        out[g * OUT_DIM + t] = a2;
    }
}

// ---------------- launch ----------------
extern "C" void kernel_launch(void* const* d_in, const int* in_sizes, int n_in,
                              void* d_out, int out_size) {
    const float* x           = (const float*)d_in[0];
    const int*   edge_index  = (const int*)d_in[1];
    const int*   gu2         = (const int*)d_in[3];
    const int*   gv2         = (const int*)d_in[4];
    const float* iso2        = (const float*)d_in[5];
    const int*   two_edges   = (const int*)d_in[6];
    const int*   ga3         = (const int*)d_in[8];
    const int*   gb3         = (const int*)d_in[9];
    const int*   gc3         = (const int*)d_in[10];
    const float* iso3        = (const float*)d_in[11];
    const int*   three_edges = (const int*)d_in[12];
    const float* g1W1_0 = (const float*)d_in[14];
    const float* g1W2_0 = (const float*)d_in[15];
    const float* g1W1_1 = (const float*)d_in[16];
    const float* g1W2_1 = (const float*)d_in[17];
    const float* g1W1_2 = (const float*)d_in[18];
    const float* g1W2_2 = (const float*)d_in[19];
    const float* g2W1_0 = (const float*)d_in[20];
    const float* g2W2_0 = (const float*)d_in[21];
    const float* g2W1_1 = (const float*)d_in[22];
    const float* g2W2_1 = (const float*)d_in[23];
    const float* g3W1_0 = (const float*)d_in[24];
    const float* g3W2_0 = (const float*)d_in[25];
    const float* g3W1_1 = (const float*)d_in[26];
    const float* g3W2_1 = (const float*)d_in[27];
    const float* cW1    = (const float*)d_in[28];
    const float* cb1    = (const float*)d_in[29];
    const float* cW2    = (const float*)d_in[30];
    const float* cb2    = (const float*)d_in[31];
    float* out = (float*)d_out;

    const int E1 = in_sizes[1] / 2;
    const int E2 = in_sizes[6] / 2;
    const int E3 = in_sizes[12] / 2;

    float *hA, *hB, *msg1, *y2, *msg2, *h2, *y3, *msg3, *h3, *emb, *Wt;
    int *cnt2, *csr2, *cnt3, *csr3;
    cudaGetSymbolAddress((void**)&hA,   d_hA);
    cudaGetSymbolAddress((void**)&hB,   d_hB);
    cudaGetSymbolAddress((void**)&msg1, d_msg1);
    cudaGetSymbolAddress((void**)&y2,   d_y2);
    cudaGetSymbolAddress((void**)&msg2, d_msg2);
    cudaGetSymbolAddress((void**)&h2,   d_h2);
    cudaGetSymbolAddress((void**)&y3,   d_y3);
    cudaGetSymbolAddress((void**)&msg3, d_msg3);
    cudaGetSymbolAddress((void**)&h3,   d_h3);
    cudaGetSymbolAddress((void**)&emb,  d_emb);
    cudaGetSymbolAddress((void**)&Wt,   d_Wt);
    cudaGetSymbolAddress((void**)&cnt2, d_cnt2);
    cudaGetSymbolAddress((void**)&csr2, d_csr2);
    cudaGetSymbolAddress((void**)&cnt3, d_cnt3);
    cudaGetSymbolAddress((void**)&csr3, d_csr3);

    // dynamic smem opt-in
    const int SM_K192 = (128 * 100 + 96 * 136 + 512) * 4;   // 105472 -> 2 CTAs/SM
    const int SM_K128 = (128 * 68  + 64 * 136 + 128) * 4;   // 70144
    const int SM_K64  = (128 * 68  + 64 * 136) * 4;         // 69632
    cudaFuncSetAttribute((const void*)gemm_mma<192, 96, 3>,
                         cudaFuncAttributeMaxDynamicSharedMemorySize, SM_K192);
    cudaFuncSetAttribute((const void*)gemm_mma<128, 64, 2>,
                         cudaFuncAttributeMaxDynamicSharedMemorySize, SM_K128);
    cudaFuncSetAttribute((const void*)gemm_mma<64, 64, 0>,
                         cudaFuncAttributeMaxDynamicSharedMemorySize, SM_K64);

    // ---- streams/events for forked capture (host-side only; re-created per call) ----
    cudaStream_t s2;
    cudaStreamCreateWithFlags(&s2, cudaStreamNonBlocking);
    cudaEvent_t evPrep, evCsr, evH1, evL2;
    cudaEventCreateWithFlags(&evPrep, cudaEventDisableTiming);
    cudaEventCreateWithFlags(&evCsr,  cudaEventDisableTiming);
    cudaEventCreateWithFlags(&evH1,   cudaEventDisableTiming);
    cudaEventCreateWithFlags(&evL2,   cudaEventDisableTiming);

    // ---- prep (default stream) ----
    WPrepAll P;
    P.w1[0] = g1W1_0; P.w2[0] = g1W2_0; P.K[0] = 32; P.off[0] = 0;
    P.w1[1] = g1W1_1; P.w2[1] = g1W2_1; P.K[1] = 64; P.off[1] = 32;
    P.w1[2] = g1W1_2; P.w2[2] = g1W2_2; P.K[2] = 64; P.off[2] = 96;
    prep_all<<<ZB3 + 4, 256>>>(P, Wt, cnt2, cnt3, emb);
    cudaEventRecord(evPrep, 0);

    // ---- fork: CSR builds on s2, overlapped with level-1 ----
    cudaStreamWaitEvent(s2, evPrep, 0);
    {
        const int blocks2 = (E2 + 1023) / 1024;
        const int blocks3 = (E3 + 1023) / 1024;
        csr_fill2<<<blocks2 + blocks3, 256, 0, s2>>>(
            two_edges + E2, two_edges, E2, cnt2, csr2,
            three_edges + E3, three_edges, E3, cnt3, csr3, blocks2);
    }
    cudaEventRecord(evCsr, s2);

    const int* e1s = edge_index;  const int* e1d = edge_index + E1;
    auto sc_grid = [](int E) { return (int)(((long long)E * 16 + 255) / 256); };
    auto ga_grid = [](int N) { return (int)(((long long)N * 16 + 255) / 256); };

    const size_t sm32 = (64 * 32 + 32 * 128) * 4;
    const size_t sm64 = (64 * 64 + 32 * 128) * 4;

    // ---- level 1 (default stream); hA holds PRE-activation ----
    gemm_dual<32><<<NNODES / 64, 256, sm32>>>(x, Wt + 0 * 128, hA, msg1, 0);
    scatter_add<<<sc_grid(E1), 256>>>((const float4*)msg1, e1s, e1d, E1, hA);

    gemm_dual<64><<<NNODES / 64, 256, sm64>>>(hA, Wt + 32 * 128, hB, msg1, 1);
    scatter_add<<<sc_grid(E1), 256>>>((const float4*)msg1, e1s, e1d, E1, hB);

    gemm_dual<64><<<NNODES / 64, 256, sm64>>>(hB, Wt + 96 * 128, hA, msg1, 1);
    scatter_add<<<sc_grid(E1), 256>>>((const float4*)msg1, e1s, e1d, E1, hA);

    seg_reduce<<<GG, 256>>>(hA, NPER, emb, 0);
    cudaEventRecord(evH1, 0);

    // ---- level 2 chain on s2 (needs hA + csr2; csr2 in-order on s2) ----
    cudaStreamWaitEvent(s2, evH1, 0);
    gemm_mma<128, 64, 2><<<N2 / 128, 256, SM_K128, s2>>>(
        hA, gu2, gv2, nullptr, iso2, g2W1_0, g2W2_0, 129, y2, msg2, 1);
    gather_add<<<ga_grid(N2), 256, 0, s2>>>((const float4*)y2, (const float4*)msg2,
                                            cnt2, csr2, N2, (float4*)h2);
    gemm_mma<64, 64, 0><<<N2 / 128, 256, SM_K64, s2>>>(
        h2, nullptr, nullptr, nullptr, nullptr, g2W1_1, g2W2_1, 64, y2, msg2, 1);
    gather_emb<<<ga_grid(N2), 256, 0, s2>>>((const float4*)y2, (const float4*)msg2,
                                            cnt2, csr2, N2, P2, emb, H);
    cudaEventRecord(evL2, s2);

    // ---- level 3 chain on default stream (concurrent with level 2) ----
    gemm_mma<192, 96, 3><<<N3 / 128, 256, SM_K192>>>(hA, ga3, gb3, gc3, iso3,
                                                     g3W1_0, g3W2_0, 196,
                                                     y3, msg3, 1);
    cudaStreamWaitEvent(0, evCsr, 0);   // csr3 ready before gather
    gather_add<<<ga_grid(N3), 256>>>((const float4*)y3, (const float4*)msg3,
                                     cnt3, csr3, N3, (float4*)h3);
    gemm_mma<64, 64, 0><<<N3 / 128, 256, SM_K64>>>(h3, nullptr, nullptr, nullptr, nullptr,
                                                   g3W1_1, g3W2_1, 64,
                                                   y3, msg3, 1);
    gather_emb<<<ga_grid(N3), 256>>>((const float4*)y3, (const float4*)msg3,
                                     cnt3, csr3, N3, P3, emb, 2 * H);

    // ---- join + head ----
    cudaStreamWaitEvent(0, evL2, 0);
    head<<<GG, H>>>(emb, cW1, cb1, cW2, cb2, out);

    cudaEventDestroy(evPrep);
    cudaEventDestroy(evCsr);
    cudaEventDestroy(evH1);
    cudaEventDestroy(evL2);
    cudaStreamDestroy(s2);
}